// round 3
// baseline (speedup 1.0000x reference)
#include <cuda_runtime.h>
#include <math.h>

#define NN 50000
#define EE 800000
#define ETOT (EE + NN)
#define NEG_SLOPE 0.2f
#define EPS 1e-16f

// ---------------- scratch (static device globals; no allocation) ----------------
__device__ __align__(16) float g_h1[NN * 128];     // layer1 pre-aggregation features
__device__ __align__(16) float g_out1[NN * 128];   // layer1 output (post ELU)
__device__ __align__(16) float g_as1[NN * 4];      // a_src layer1
__device__ __align__(16) float g_ad1[NN * 4];      // a_dst layer1
__device__ __align__(16) float g_h2[NN * 2];
__device__ float g_as2[NN];
__device__ float g_ad2[NN];
__device__ int g_deg[NN];
__device__ int g_off[NN + 1];
__device__ int g_cur[NN];
__device__ int g_src[ETOT];
__device__ int g_is64;   // 1 if edge_index is int64, 0 if int32

// ---------------- helpers ----------------
__device__ __forceinline__ float lrelu(float x) {
    return x > 0.0f ? x : NEG_SLOPE * x;
}

__device__ __forceinline__ float warp_max(float v) {
    #pragma unroll
    for (int o = 16; o; o >>= 1) v = fmaxf(v, __shfl_xor_sync(0xFFFFFFFFu, v, o));
    return v;
}
__device__ __forceinline__ float warp_sum(float v) {
    #pragma unroll
    for (int o = 16; o; o >>= 1) v += __shfl_xor_sync(0xFFFFFFFFu, v, o);
    return v;
}

// edge index fetch honoring runtime dtype
__device__ __forceinline__ int edge_at(const void* ei, int idx, int is64) {
    if (is64) return (int)((const long long*)ei)[idx];
    return ((const int*)ei)[idx];
}

// ---------------- dtype sniff ----------------
// int64 node ids < 2^31 have zero high words. If ANY of the first 1024 odd
// int32 words is nonzero, the buffer must be int32 (two ids per 8 bytes).
__global__ void sniff_kernel(const int* __restrict__ ei32, int nwords) {
    if (threadIdx.x == 0 && blockIdx.x == 0) {
        int is64 = 1;
        int lim = min(nwords, 2048);
        for (int w = 1; w < lim; w += 2) {
            if (ei32[w] != 0) { is64 = 0; break; }
        }
        g_is64 = is64;
    }
}

// ---------------- CSR build ----------------
__global__ void init_deg_kernel(int n) {
    int i = blockIdx.x * blockDim.x + threadIdx.x;
    if (i < n) g_deg[i] = 1;  // self-loop
}

__global__ void hist_kernel(const void* __restrict__ ei, int e) {
    int i = blockIdx.x * blockDim.x + threadIdx.x;
    int is64 = g_is64;
    if (i < e) {
        int dst = edge_at(ei, e + i, is64);
        atomicAdd(&g_deg[dst], 1);
    }
}

__global__ void scan_kernel(int n) {
    // single block, 1024 threads
    __shared__ int sh[1024];
    const int C = (n + 1023) / 1024;
    int t = threadIdx.x;
    int lo = t * C, hi = min(lo + C, n);
    int s = 0;
    for (int i = lo; i < hi; i++) s += g_deg[i];
    sh[t] = s;
    __syncthreads();
    // inclusive Hillis-Steele
    for (int o = 1; o < 1024; o <<= 1) {
        int v = (t >= o) ? sh[t - o] : 0;
        __syncthreads();
        sh[t] += v;
        __syncthreads();
    }
    int run = (t > 0) ? sh[t - 1] : 0;
    for (int i = lo; i < hi; i++) {
        g_off[i] = run;
        g_cur[i] = run;
        run += g_deg[i];
    }
    if (t == 1023) g_off[n] = sh[1023];
}

__global__ void scatter_kernel(const void* __restrict__ ei, int e, int n) {
    int i = blockIdx.x * blockDim.x + threadIdx.x;
    int is64 = g_is64;
    if (i < e) {
        int dst = edge_at(ei, e + i, is64);
        int src = edge_at(ei, i, is64);
        int pos = atomicAdd(&g_cur[dst], 1);
        g_src[pos] = src;
    } else if (i < e + n) {
        int v = i - e;
        int pos = atomicAdd(&g_cur[v], 1);
        g_src[pos] = v;  // self loop
    }
}

// ---------------- GEMM1: h1 = x @ W1  (N x 128 @ 128 x 128) ----------------
// block: 256 threads, tile 64 rows x 128 cols, k-steps of 32
__global__ void gemm1_kernel(const float* __restrict__ x,
                             const float* __restrict__ W1, int n) {
    __shared__ float As[64][32];
    __shared__ float Bs[32][128];
    int tid = threadIdx.x;
    int row0 = blockIdx.x * 64;
    int cgrp = (tid & 31) * 4;       // 4 consecutive cols
    int rgrp = (tid >> 5) * 8;       // 8 rows

    float acc[8][4];
    #pragma unroll
    for (int r = 0; r < 8; r++)
        #pragma unroll
        for (int c = 0; c < 4; c++) acc[r][c] = 0.0f;

    for (int kk = 0; kk < 4; kk++) {
        // load A tile (64x32)
        #pragma unroll
        for (int i = 0; i < 8; i++) {
            int idx = tid + i * 256;
            int r = idx >> 5, k = idx & 31;
            int gr = row0 + r;
            As[r][k] = (gr < n) ? x[gr * 128 + kk * 32 + k] : 0.0f;
        }
        // load B tile (32x128)
        #pragma unroll
        for (int i = 0; i < 16; i++) {
            int idx = tid + i * 256;
            int k = idx >> 7, c = idx & 127;
            Bs[k][c] = W1[(kk * 32 + k) * 128 + c];
        }
        __syncthreads();
        #pragma unroll
        for (int k = 0; k < 32; k++) {
            float4 b = *(const float4*)&Bs[k][cgrp];
            #pragma unroll
            for (int r = 0; r < 8; r++) {
                float a = As[rgrp + r][k];
                acc[r][0] += a * b.x;
                acc[r][1] += a * b.y;
                acc[r][2] += a * b.z;
                acc[r][3] += a * b.w;
            }
        }
        __syncthreads();
    }
    #pragma unroll
    for (int r = 0; r < 8; r++) {
        int gr = row0 + rgrp + r;
        if (gr < n) {
            float4 v = make_float4(acc[r][0], acc[r][1], acc[r][2], acc[r][3]);
            *(float4*)&g_h1[gr * 128 + cgrp] = v;
        }
    }
}

// ---------------- attention coefficients layer 1 ----------------
// warp per node: a_src[n][h] = sum_c h1[n][h*32+c]*att_src1[h*32+c]
__global__ void att1_kernel(const float* __restrict__ att_src1,
                            const float* __restrict__ att_dst1, int n) {
    int warp = (blockIdx.x * blockDim.x + threadIdx.x) >> 5;
    int lane = threadIdx.x & 31;
    if (warp >= n) return;
    const float* hp = g_h1 + warp * 128;
    #pragma unroll
    for (int h = 0; h < 4; h++) {
        float v = hp[h * 32 + lane];
        float ps = v * att_src1[h * 32 + lane];
        float pd = v * att_dst1[h * 32 + lane];
        ps = warp_sum(ps);
        pd = warp_sum(pd);
        if (lane == 0) {
            g_as1[warp * 4 + h] = ps;
            g_ad1[warp * 4 + h] = pd;
        }
    }
}

// ---------------- layer-1 aggregation: warp per destination node ----------------
__global__ void aggr1_kernel(const float* __restrict__ b1, int n) {
    int node = (blockIdx.x * blockDim.x + threadIdx.x) >> 5;
    int lane = threadIdx.x & 31;
    if (node >= n) return;
    int start = g_off[node], end = g_off[node + 1];
    const float4* aS = (const float4*)g_as1;
    float4 ad = ((const float4*)g_ad1)[node];

    // phase 1: per-head max over edges (lanes over edges)
    float4 m = make_float4(-INFINITY, -INFINITY, -INFINITY, -INFINITY);
    for (int i = start + lane; i < end; i += 32) {
        int s = __ldg(&g_src[i]);
        float4 as = aS[s];
        m.x = fmaxf(m.x, lrelu(as.x + ad.x));
        m.y = fmaxf(m.y, lrelu(as.y + ad.y));
        m.z = fmaxf(m.z, lrelu(as.z + ad.z));
        m.w = fmaxf(m.w, lrelu(as.w + ad.w));
    }
    m.x = warp_max(m.x); m.y = warp_max(m.y);
    m.z = warp_max(m.z); m.w = warp_max(m.w);

    // phase 2+3 merged: unnormalized weights + feature accumulation
    // (division by denom hoisted out of the loop: exact algebraic identity)
    float acc0 = 0.f, acc1 = 0.f, acc2 = 0.f, acc3 = 0.f;
    float4 ss = make_float4(0.f, 0.f, 0.f, 0.f);
    for (int j = start; j < end; j++) {
        int s = __ldg(&g_src[j]);                 // broadcast load
        float4 as = aS[s];                        // broadcast (same addr all lanes)
        float e0 = __expf(lrelu(as.x + ad.x) - m.x);
        float e1 = __expf(lrelu(as.y + ad.y) - m.y);
        float e2 = __expf(lrelu(as.z + ad.z) - m.z);
        float e3 = __expf(lrelu(as.w + ad.w) - m.w);
        ss.x += e0; ss.y += e1; ss.z += e2; ss.w += e3;
        const float* hp = g_h1 + s * 128 + lane;
        acc0 += e0 * hp[0];
        acc1 += e1 * hp[32];
        acc2 += e2 * hp[64];
        acc3 += e3 * hp[96];
    }
    float o0 = acc0 / (ss.x + EPS) + b1[lane];
    float o1 = acc1 / (ss.y + EPS) + b1[32 + lane];
    float o2 = acc2 / (ss.z + EPS) + b1[64 + lane];
    float o3 = acc3 / (ss.w + EPS) + b1[96 + lane];
    // ELU
    o0 = o0 > 0.f ? o0 : (__expf(o0) - 1.0f);
    o1 = o1 > 0.f ? o1 : (__expf(o1) - 1.0f);
    o2 = o2 > 0.f ? o2 : (__expf(o2) - 1.0f);
    o3 = o3 > 0.f ? o3 : (__expf(o3) - 1.0f);
    float* op = g_out1 + node * 128 + lane;
    op[0] = o0; op[32] = o1; op[64] = o2; op[96] = o3;
}

// ---------------- layer 2: GEMM (128->2) + attention coefficients ----------------
__global__ void gemm2att_kernel(const float* __restrict__ W2,
                                const float* __restrict__ att_src2,
                                const float* __restrict__ att_dst2, int n) {
    int node = (blockIdx.x * blockDim.x + threadIdx.x) >> 5;
    int lane = threadIdx.x & 31;
    if (node >= n) return;
    float a0 = 0.f, a1 = 0.f;
    const float* op = g_out1 + node * 128;
    #pragma unroll
    for (int j = 0; j < 4; j++) {
        int k = lane + 32 * j;
        float v = op[k];
        a0 += v * __ldg(&W2[k * 2 + 0]);
        a1 += v * __ldg(&W2[k * 2 + 1]);
    }
    a0 = warp_sum(a0);
    a1 = warp_sum(a1);
    if (lane == 0) {
        g_h2[node * 2 + 0] = a0;
        g_h2[node * 2 + 1] = a1;
        g_as2[node] = a0 * att_src2[0] + a1 * att_src2[1];
        g_ad2[node] = a0 * att_dst2[0] + a1 * att_dst2[1];
    }
}

// ---------------- layer-2 aggregation + bias + log_softmax ----------------
__global__ void aggr2_kernel(const float* __restrict__ b2,
                             float* __restrict__ out, int n) {
    int node = (blockIdx.x * blockDim.x + threadIdx.x) >> 5;
    int lane = threadIdx.x & 31;
    if (node >= n) return;
    int start = g_off[node], end = g_off[node + 1];
    float ad = g_ad2[node];

    float m = -INFINITY;
    for (int i = start + lane; i < end; i += 32) {
        int s = __ldg(&g_src[i]);
        m = fmaxf(m, lrelu(g_as2[s] + ad));
    }
    m = warp_max(m);

    float sum = 0.f, acc0 = 0.f, acc1 = 0.f;
    for (int i = start + lane; i < end; i += 32) {
        int s = __ldg(&g_src[i]);
        float ex = __expf(lrelu(g_as2[s] + ad) - m);
        sum += ex;
        acc0 += ex * g_h2[s * 2 + 0];
        acc1 += ex * g_h2[s * 2 + 1];
    }
    sum = warp_sum(sum);
    acc0 = warp_sum(acc0);
    acc1 = warp_sum(acc1);

    if (lane == 0) {
        float o0 = acc0 / (sum + EPS) + b2[0];
        float o1 = acc1 / (sum + EPS) + b2[1];
        float mx = fmaxf(o0, o1);
        float lse = mx + __logf(__expf(o0 - mx) + __expf(o1 - mx));
        out[node * 2 + 0] = o0 - lse;
        out[node * 2 + 1] = o1 - lse;
    }
}

// ---------------- launch ----------------
extern "C" void kernel_launch(void* const* d_in, const int* in_sizes, int n_in,
                              void* d_out, int out_size) {
    const float* x         = (const float*)d_in[0];
    const void*  ei        = (const void*)d_in[1];
    const float* W1        = (const float*)d_in[2];
    const float* att_src1  = (const float*)d_in[3];
    const float* att_dst1  = (const float*)d_in[4];
    const float* b1        = (const float*)d_in[5];
    const float* W2        = (const float*)d_in[6];
    const float* att_src2  = (const float*)d_in[7];
    const float* att_dst2  = (const float*)d_in[8];
    const float* b2        = (const float*)d_in[9];
    float* out             = (float*)d_out;

    int n = in_sizes[0] / 128;   // 50000
    int e = in_sizes[1] / 2;     // 800000 (element count is dtype-independent here)

    sniff_kernel<<<1, 32>>>((const int*)ei, in_sizes[1]);
    init_deg_kernel<<<(n + 255) / 256, 256>>>(n);
    hist_kernel<<<(e + 255) / 256, 256>>>(ei, e);
    scan_kernel<<<1, 1024>>>(n);
    scatter_kernel<<<(e + n + 255) / 256, 256>>>(ei, e, n);

    gemm1_kernel<<<(n + 63) / 64, 256>>>(x, W1, n);
    att1_kernel<<<(n * 32 + 255) / 256, 256>>>(att_src1, att_dst1, n);
    aggr1_kernel<<<(n * 32 + 255) / 256, 256>>>(b1, n);
    gemm2att_kernel<<<(n * 32 + 255) / 256, 256>>>(W2, att_src2, att_dst2, n);
    aggr2_kernel<<<(n * 32 + 255) / 256, 256>>>(b2, out, n);
}